// round 13
// baseline (speedup 1.0000x reference)
#include <cuda_runtime.h>
#include <math.h>

// Mamba 6-branch fused pipeline, fp32, chunked parallel scan, f32x2-packed.
// LC=32 chunks, pipelined x loads, template-specialized permutation address math.
#define LSEQ 2048
#define DI   512
#define NIB  12
#define LC   32
#define NCH  64

typedef unsigned long long ull;

// -------- scratch (device globals) --------
__device__ float g_xz[2 * LSEQ * 1024];        // [b][l][e]
__device__ float g_dtlow[NIB * LSEQ * 16];     // [ib][t][r]
__device__ float g_bcs[NIB * LSEQ * 32];       // [ib][t][s] s<16:B, s>=16:C
__device__ float g_P[NIB * NCH * DI * 16];
__device__ float g_q[NIB * NCH * DI * 16];
__device__ float g_hin[NIB * NCH * DI * 16];
__device__ float g_total[2 * LSEQ * DI];       // [b][l][d]

__device__ __forceinline__ float silu_f(float v) {
    float e = __expf(-fabsf(v));
    return ((v >= 0.f) ? v : v * e) / (1.f + e);
}
__device__ __forceinline__ int perm_idx(int tau, int rev, int sft, int msk) {
    int base = rev ? (2047 - tau) : tau;
    return ((base & msk) << (11 - sft)) | (base >> sft);
}
__device__ __forceinline__ ull pack2(float lo, float hi) {
    ull r; asm("mov.b64 %0, {%1,%2};" : "=l"(r) : "f"(lo), "f"(hi)); return r;
}
__device__ __forceinline__ void ffma2(ull& d, ull a, ull b) {       // d = a*b + d
    asm("fma.rn.f32x2 %0, %1, %2, %0;" : "+l"(d) : "l"(a), "l"(b));
}
__device__ __forceinline__ ull ffma2_3(ull a, ull b, ull c) {       // a*b + c
    ull r; asm("fma.rn.f32x2 %0, %1, %2, %3;" : "=l"(r) : "l"(a), "l"(b), "l"(c)); return r;
}
__device__ __forceinline__ ull fmul2(ull a, ull b) {
    ull r; asm("mul.rn.f32x2 %0, %1, %2;" : "=l"(r) : "l"(a), "l"(b)); return r;
}
__device__ __forceinline__ float2 unpack2(ull v) {
    float2 f; asm("mov.b64 {%0,%1}, %2;" : "=f"(f.x), "=f"(f.y) : "l"(v)); return f;
}

// ---------------- K0: zero g_total ----------------
__global__ void __launch_bounds__(256) k0_zero()
{
    int gid = blockIdx.x * 256 + threadIdx.x;
    *(float4*)&g_total[(size_t)gid * 4] = make_float4(0.f, 0.f, 0.f, 0.f);
}

// ---------------- K1: xz[m][e] = sum_k hs[m][k]*in_w[e][k] (M=4096,N=1024,K=256) ----------------
__global__ void __launch_bounds__(256) k1_gemm_in(const float* __restrict__ hs,
                                                  const float* __restrict__ in_w)
{
    __shared__ __align__(16) float sa[16][132];
    __shared__ __align__(16) float sb[16][132];
    int m0 = blockIdx.x * 128, n0 = blockIdx.y * 128;
    int tid = threadIdx.x;
    int tx = tid & 15, ty = tid >> 4;
    ull acc[8][4];
#pragma unroll
    for (int ii = 0; ii < 8; ii++)
#pragma unroll
        for (int jj = 0; jj < 4; jj++) acc[ii][jj] = 0ull;
    int rowa = tid >> 1, kh = (tid & 1) * 8;
    for (int k0 = 0; k0 < 256; k0 += 16) {
#pragma unroll
        for (int q = 0; q < 2; q++) {
            float4 v = *(const float4*)&hs[(size_t)(m0 + rowa) * 256 + k0 + kh + q * 4];
            sa[kh + q * 4 + 0][rowa] = v.x; sa[kh + q * 4 + 1][rowa] = v.y;
            sa[kh + q * 4 + 2][rowa] = v.z; sa[kh + q * 4 + 3][rowa] = v.w;
            float4 w = *(const float4*)&in_w[(size_t)(n0 + rowa) * 256 + k0 + kh + q * 4];
            sb[kh + q * 4 + 0][rowa] = w.x; sb[kh + q * 4 + 1][rowa] = w.y;
            sb[kh + q * 4 + 2][rowa] = w.z; sb[kh + q * 4 + 3][rowa] = w.w;
        }
        __syncthreads();
#pragma unroll
        for (int kk = 0; kk < 16; kk++) {
            float4 a0 = *(float4*)&sa[kk][ty * 8];
            float4 a1 = *(float4*)&sa[kk][ty * 8 + 4];
            float4 b0 = *(float4*)&sb[kk][tx * 8];
            float4 b1 = *(float4*)&sb[kk][tx * 8 + 4];
            ull bp[4] = {pack2(b0.x, b0.y), pack2(b0.z, b0.w),
                         pack2(b1.x, b1.y), pack2(b1.z, b1.w)};
            float av[8] = {a0.x, a0.y, a0.z, a0.w, a1.x, a1.y, a1.z, a1.w};
#pragma unroll
            for (int ii = 0; ii < 8; ii++) {
                ull ap = pack2(av[ii], av[ii]);
#pragma unroll
                for (int jj = 0; jj < 4; jj++) ffma2(acc[ii][jj], ap, bp[jj]);
            }
        }
        __syncthreads();
    }
#pragma unroll
    for (int ii = 0; ii < 8; ii++) {
        float2 c0 = unpack2(acc[ii][0]), c1 = unpack2(acc[ii][1]);
        float2 c2 = unpack2(acc[ii][2]), c3 = unpack2(acc[ii][3]);
        float4 v0 = make_float4(c0.x, c0.y, c1.x, c1.y);
        float4 v1 = make_float4(c2.x, c2.y, c3.x, c3.y);
        size_t base = (size_t)(m0 + ty * 8 + ii) * 1024 + n0 + tx * 8;
        *(float4*)&g_xz[base]     = v0;
        *(float4*)&g_xz[base + 4] = v1;
    }
}

// ---------------- K3a: fused conv+silu u, x_dbl[ib][t][r] = sum_d u[t][d]*xproj_w[i][r][d] ----------------
__global__ void __launch_bounds__(256) k3a_xproj(const float* __restrict__ xproj_w,
                                                 const float* __restrict__ conv_w,
                                                 const float* __restrict__ conv_b)
{
    __shared__ float su[64][65];
    __shared__ float sw[48][65];
    int ib = blockIdx.y, i = ib >> 1, b = ib & 1;
    int t0 = blockIdx.x * 64;
    int tid = threadIdx.x;
    int tx = tid & 15, ty = tid >> 4;
    int sft = (i < 2) ? 11 : ((i < 4) ? 6 : 4);
    int rev = i & 1;
    int msk = (1 << sft) - 1;
    const float* xb = g_xz + (size_t)b * LSEQ * 1024;
    ull acc2[2][3];
#pragma unroll
    for (int ii = 0; ii < 2; ii++)
#pragma unroll
        for (int j = 0; j < 3; j++) acc2[ii][j] = 0ull;

    for (int dk = 0; dk < 512; dk += 64) {
#pragma unroll
        for (int p = 0; p < 4; p++) {
            int lin = tid + p * 256;
            int tt = lin >> 4, dq = (lin & 15) * 4;
            int dcol = dk + dq;
            float4 wv0 = *(const float4*)&conv_w[((size_t)i * 512 + dcol + 0) * 4];
            float4 wv1 = *(const float4*)&conv_w[((size_t)i * 512 + dcol + 1) * 4];
            float4 wv2 = *(const float4*)&conv_w[((size_t)i * 512 + dcol + 2) * 4];
            float4 wv3 = *(const float4*)&conv_w[((size_t)i * 512 + dcol + 3) * 4];
            float4 a = *(const float4*)&conv_b[i * 512 + dcol];
#pragma unroll
            for (int k = 0; k < 4; k++) {
                int tau = t0 + tt - 3 + k;
                if (tau >= 0) {
                    int l = perm_idx(tau, rev, sft, msk);
                    float4 xv = *(const float4*)&xb[(size_t)l * 1024 + dcol];
                    float w0 = (k == 0) ? wv0.x : (k == 1) ? wv0.y : (k == 2) ? wv0.z : wv0.w;
                    float w1 = (k == 0) ? wv1.x : (k == 1) ? wv1.y : (k == 2) ? wv1.z : wv1.w;
                    float w2 = (k == 0) ? wv2.x : (k == 1) ? wv2.y : (k == 2) ? wv2.z : wv2.w;
                    float w3 = (k == 0) ? wv3.x : (k == 1) ? wv3.y : (k == 2) ? wv3.z : wv3.w;
                    a.x = fmaf(w0, xv.x, a.x);
                    a.y = fmaf(w1, xv.y, a.y);
                    a.z = fmaf(w2, xv.z, a.z);
                    a.w = fmaf(w3, xv.w, a.w);
                }
            }
            su[tt][dq + 0] = silu_f(a.x);
            su[tt][dq + 1] = silu_f(a.y);
            su[tt][dq + 2] = silu_f(a.z);
            su[tt][dq + 3] = silu_f(a.w);
        }
#pragma unroll
        for (int p = 0; p < 3; p++) {
            int lin = tid + p * 256;
            int r = lin >> 4, dq = lin & 15;
            float4 v = *(const float4*)&xproj_w[((size_t)i * 48 + r) * 512 + dk + dq * 4];
            sw[r][dq * 4 + 0] = v.x; sw[r][dq * 4 + 1] = v.y;
            sw[r][dq * 4 + 2] = v.z; sw[r][dq * 4 + 3] = v.w;
        }
        __syncthreads();
#pragma unroll 8
        for (int dd = 0; dd < 64; dd++) {
            ull up0 = pack2(su[tx * 4 + 0][dd], su[tx * 4 + 1][dd]);
            ull up1 = pack2(su[tx * 4 + 2][dd], su[tx * 4 + 3][dd]);
#pragma unroll
            for (int j = 0; j < 3; j++) {
                float wvv = sw[ty * 3 + j][dd];
                ull wvp = pack2(wvv, wvv);
                ffma2(acc2[0][j], up0, wvp);
                ffma2(acc2[1][j], up1, wvp);
            }
        }
        __syncthreads();
    }
#pragma unroll
    for (int j = 0; j < 3; j++) {
        float2 lo = unpack2(acc2[0][j]);
        float2 hi = unpack2(acc2[1][j]);
        float vals[4] = {lo.x, lo.y, hi.x, hi.y};
        int r = ty * 3 + j;
#pragma unroll
        for (int ii = 0; ii < 4; ii++) {
            int t = t0 + tx * 4 + ii;
            float v = vals[ii];
            if (r < 16) g_dtlow[((size_t)ib * LSEQ + t) * 16 + r] = v;
            else        g_bcs[((size_t)ib * LSEQ + t) * 32 + (r - 16)] = v;
        }
    }
}

// ---------------- scan shared staging ----------------
struct __align__(16) ScanShared {
    float sdt[32][20];
    float sbc[32][36];
};

__device__ __forceinline__ void stage_tile(ScanShared* sh, int ib, int tb, int tid, bool passc)
{
    __syncthreads();
    if (tid < 128) {
        int tt = tid >> 2, r4 = (tid & 3) * 4;
        *(float4*)&sh->sdt[tt][r4] =
            *(const float4*)&g_dtlow[((size_t)ib * LSEQ + tb + tt) * 16 + r4];
    }
    if (passc) {
        int tt = tid >> 3, s4 = (tid & 7) * 4;
        *(float4*)&sh->sbc[tt][s4] =
            *(const float4*)&g_bcs[((size_t)ib * LSEQ + tb + tt) * 32 + s4];
    } else if (tid >= 128) {
        int q = tid - 128;
        int tt = q >> 2, r4 = (q & 3) * 4;
        *(float4*)&sh->sbc[tt][r4] =
            *(const float4*)&g_bcs[((size_t)ib * LSEQ + tb + tt) * 32 + r4];
    }
    __syncthreads();
}

// ---------------- fast (A[n]=-(n+1)) scan body; SFT/REV compile-time specialized ----------------
template<int SFT, bool REV, bool PASSC>
__device__ __forceinline__ void scan_fast(
    ScanShared* sh, int ib, int b, int c, int d, int tid,
    float4 wv, float cbv, const ull* dtw2, float dtb,
    float Dsk, ull* h2, float* Sout)
{
    constexpr int MSK = (1 << SFT) - 1;
    constexpr int LSTRIDE = (REV ? -1 : 1) * (1 << (11 - SFT));
    constexpr int RMASK = (SFT == 6) ? 31 : 15;   // recompute period (unused for SFT=11)
    const float* xb = g_xz + (size_t)b * LSEQ * 1024 + d;
    const float* zb = xb + 512;
    float x3 = 0.f, x2 = 0.f, x1 = 0.f;
    int t0c = c * LC;
    if (t0c >= 3) {
        x3 = xb[(size_t)perm_idx(t0c - 3, REV, SFT, MSK) * 1024];
        x2 = xb[(size_t)perm_idx(t0c - 2, REV, SFT, MSK) * 1024];
        x1 = xb[(size_t)perm_idx(t0c - 1, REV, SFT, MSK) * 1024];
    }
    int l = perm_idx(t0c, REV, SFT, MSK);
    float xcur = xb[(size_t)l * 1024];
    float S = 0.f;
    float* totb = g_total + (size_t)b * LSEQ * 512 + d;
    for (int sub = 0; sub < LC / 32; sub++) {
        int tb = t0c + sub * 32;
        stage_tile(sh, ib, tb, tid, PASSC);
#pragma unroll 2
        for (int tt = 0; tt < 32; tt++) {
            int t = tb + tt;
            int tn = t + 1;
            // incremental permuted address for next step
            int lnext;
            if (SFT == 11) lnext = l + LSTRIDE;
            else lnext = ((tn & RMASK) == 0) ? perm_idx(tn, REV, SFT, MSK) : (l + LSTRIDE);
            float xnext = (tn < 2048) ? xb[(size_t)lnext * 1024] : 0.f;
            float ua = fmaf(wv.x, x3, fmaf(wv.y, x2, fmaf(wv.z, x1, fmaf(wv.w, xcur, cbv))));
            x3 = x2; x2 = x1; x1 = xcur;
            float u = silu_f(ua);
            // delta = softplus(dtw . sdt + dtb), packed dot
            const ull* qd = (const ull*)&sh->sdt[tt][0];
            ull a2 = 0ull;
#pragma unroll
            for (int j = 0; j < 8; j++) ffma2(a2, dtw2[j], qd[j]);
            float2 as_ = unpack2(a2);
            float a = dtb + as_.x + as_.y;
            float delta = fmaxf(a, 0.f) + __logf(1.f + __expf(-fabsf(a)));
            S += delta;
            // dA pairs via chained multiply
            float E = __expf(-delta);
            float E2 = E * E;
            ull e2p = pack2(E2, E2);
            ull dA = pack2(E, E2);
            float dub = delta * u;
            ull dubp = pack2(dub, dub);
            const ull* bp = (const ull*)&sh->sbc[tt][0];
            const ull* cp = (const ull*)&sh->sbc[tt][16];
            ull y2 = 0ull;
#pragma unroll
            for (int j = 0; j < 8; j++) {
                h2[j] = ffma2_3(dA, h2[j], fmul2(dubp, bp[j]));
                if (PASSC) ffma2(y2, h2[j], cp[j]);
                if (j < 7) dA = fmul2(dA, e2p);
            }
            if (PASSC) {
                float2 yy = unpack2(y2);
                float y = yy.x + yy.y;
                float z = zb[(size_t)l * 1024];
                float outv = (y + u * Dsk) * silu_f(z);
                int lout;
                if (SFT == 11 && !REV)      lout = t;
                else if (SFT == 11)         lout = 2047 - t;
                else if (SFT == 6)          lout = ((t & 63) << 5) | (t >> 6);
                else                        lout = ((t & 15) << 7) | (t >> 4);
                atomicAdd(&totb[(size_t)lout * 512], outv);
            }
            l = lnext; xcur = xnext;
        }
    }
    *Sout = S;
}

// ---------------- slow fallback (general A), scalar ----------------
template<bool PASSC>
__device__ __noinline__ void scan_slow(
    ScanShared* sh, int ib, int b, int c, int d, int tid,
    int sft, int rev, int msk,
    float4 wv, float cbv, const ull* dtw2, float dtb,
    const float* A_log, float Dsk, float* h, float* Sout)
{
    int i = ib >> 1;
    float Av[16];
#pragma unroll
    for (int n = 0; n < 16; n++) Av[n] = -__expf(A_log[((size_t)i * 512 + d) * 16 + n]);
    const float* xb = g_xz + (size_t)b * LSEQ * 1024 + d;
    const float* zb = xb + 512;
    float x3 = 0.f, x2 = 0.f, x1 = 0.f;
    int t0c = c * LC;
    if (t0c >= 3) {
        x3 = xb[(size_t)perm_idx(t0c - 3, rev, sft, msk) * 1024];
        x2 = xb[(size_t)perm_idx(t0c - 2, rev, sft, msk) * 1024];
        x1 = xb[(size_t)perm_idx(t0c - 1, rev, sft, msk) * 1024];
    }
    float S = 0.f;
    float* totb = g_total + (size_t)b * LSEQ * 512 + d;
    for (int sub = 0; sub < LC / 32; sub++) {
        int tb = t0c + sub * 32;
        stage_tile(sh, ib, tb, tid, PASSC);
        for (int tt = 0; tt < 32; tt++) {
            int t = tb + tt;
            int l = perm_idx(t, rev, sft, msk);
            float xv = xb[(size_t)l * 1024];
            float ua = fmaf(wv.x, x3, fmaf(wv.y, x2, fmaf(wv.z, x1, fmaf(wv.w, xv, cbv))));
            x3 = x2; x2 = x1; x1 = xv;
            float u = silu_f(ua);
            const ull* qd = (const ull*)&sh->sdt[tt][0];
            ull a2 = 0ull;
#pragma unroll
            for (int j = 0; j < 8; j++) ffma2(a2, dtw2[j], qd[j]);
            float2 as_ = unpack2(a2);
            float a = dtb + as_.x + as_.y;
            float delta = fmaxf(a, 0.f) + __logf(1.f + __expf(-fabsf(a)));
            S += delta;
            float dub = delta * u;
            float y = 0.f;
#pragma unroll
            for (int n = 0; n < 16; n++) {
                float bn = sh->sbc[tt][n];
                h[n] = fmaf(__expf(delta * Av[n]), h[n], dub * bn);
                if (PASSC) y = fmaf(h[n], sh->sbc[tt][16 + n], y);
            }
            if (PASSC) {
                float z = zb[(size_t)l * 1024];
                float outv = (y + u * Dsk) * silu_f(z);
                int i2 = ib >> 1;
                int lout;
                if (i2 == 0)      lout = t;
                else if (i2 == 1) lout = 2047 - t;
                else if (i2 < 4)  lout = ((t & 63) << 5) | (t >> 6);
                else              lout = ((t & 15) << 7) | (t >> 4);
                atomicAdd(&totb[(size_t)lout * 512], outv);
            }
        }
    }
    *Sout = S;
}

__device__ __forceinline__ bool check_fast(const float* A_log, int i, int d) {
    bool fast = true;
#pragma unroll
    for (int n = 0; n < 16; n++) {
        float Av = __expf(A_log[((size_t)i * 512 + d) * 16 + n]);
        fast = fast && (fabsf(Av - (float)(n + 1)) < 1e-4f * (float)(n + 1));
    }
    return fast;
}

__global__ void __launch_bounds__(256, 4) k4a_chunk(const float* __restrict__ A_log,
                                                    const float* __restrict__ conv_w,
                                                    const float* __restrict__ conv_b,
                                                    const float* __restrict__ dt_w,
                                                    const float* __restrict__ dt_b)
{
    __shared__ ScanShared sh;
    int bi = blockIdx.x;                  // 1536 = 12 ib * 64 c * 2 half
    int half = bi & 1, c = (bi >> 1) & 63, ib = bi >> 7;
    int i = ib >> 1, b = ib & 1;
    int tid = threadIdx.x;
    int d = half * 256 + tid;
    float4 wv = *(const float4*)&conv_w[((size_t)i * 512 + d) * 4];
    float cbv = conv_b[i * 512 + d];
    ull dtw2[8];
#pragma unroll
    for (int r = 0; r < 16; r += 4) {
        float4 v = *(const float4*)&dt_w[((size_t)i * 512 + d) * 16 + r];
        dtw2[r / 2]     = pack2(v.x, v.y);
        dtw2[r / 2 + 1] = pack2(v.z, v.w);
    }
    float dtb = dt_b[i * 512 + d];
    bool fast = check_fast(A_log, i, d);
    float S = 0.f;
    size_t base = (((size_t)ib * NCH + c) * 512 + d) * 16;
    if (fast) {
        ull h2[8];
#pragma unroll
        for (int j = 0; j < 8; j++) h2[j] = 0ull;
        switch (i) {
        case 0: scan_fast<11, false, false>(&sh, ib, b, c, d, tid, wv, cbv, dtw2, dtb, 0.f, h2, &S); break;
        case 1: scan_fast<11, true,  false>(&sh, ib, b, c, d, tid, wv, cbv, dtw2, dtb, 0.f, h2, &S); break;
        case 2: scan_fast<6,  false, false>(&sh, ib, b, c, d, tid, wv, cbv, dtw2, dtb, 0.f, h2, &S); break;
        case 3: scan_fast<6,  true,  false>(&sh, ib, b, c, d, tid, wv, cbv, dtw2, dtb, 0.f, h2, &S); break;
        case 4: scan_fast<4,  false, false>(&sh, ib, b, c, d, tid, wv, cbv, dtw2, dtb, 0.f, h2, &S); break;
        default: scan_fast<4, true,  false>(&sh, ib, b, c, d, tid, wv, cbv, dtw2, dtb, 0.f, h2, &S); break;
        }
        ull* qb = (ull*)&g_q[base];
#pragma unroll
        for (int j = 0; j < 8; j++) qb[j] = h2[j];
        float F = __expf(-S);
        float F2 = F * F;
        ull f2p = pack2(F2, F2);
        ull P = pack2(F, F2);
        ull* pb = (ull*)&g_P[base];
#pragma unroll
        for (int j = 0; j < 8; j++) {
            pb[j] = P;
            if (j < 7) P = fmul2(P, f2p);
        }
    } else {
        int sft = (i < 2) ? 11 : ((i < 4) ? 6 : 4);
        int rev = i & 1;
        int msk = (1 << sft) - 1;
        float h[16];
#pragma unroll
        for (int n = 0; n < 16; n++) h[n] = 0.f;
        scan_slow<false>(&sh, ib, b, c, d, tid, sft, rev, msk, wv, cbv, dtw2, dtb, A_log, 0.f, h, &S);
#pragma unroll
        for (int n = 0; n < 16; n++) {
            float Av = -__expf(A_log[((size_t)i * 512 + d) * 16 + n]);
            g_P[base + n] = __expf(Av * S);
            g_q[base + n] = h[n];
        }
    }
}

// ---------------- K4b: inter-chunk scan (64 steps, prefetched batches of 16) ----------------
__global__ void __launch_bounds__(256) k4b_carry()
{
    int gid = blockIdx.x * 256 + threadIdx.x;   // 98304 = 12*512*16
    size_t base0 = (size_t)gid % (512 * 16);
    int ib = gid / (512 * 16);
    size_t stride = (size_t)512 * 16;
    size_t b0 = (size_t)ib * NCH * stride + base0;
    float h = 0.f;
#pragma unroll
    for (int batch = 0; batch < NCH / 16; batch++) {
        float P[16], q[16];
#pragma unroll
        for (int j = 0; j < 16; j++) {
            size_t idx = b0 + (size_t)(batch * 16 + j) * stride;
            P[j] = g_P[idx];
            q[j] = g_q[idx];
        }
#pragma unroll
        for (int j = 0; j < 16; j++) {
            size_t idx = b0 + (size_t)(batch * 16 + j) * stride;
            g_hin[idx] = h;
            h = fmaf(P[j], h, q[j]);
        }
    }
}

__global__ void __launch_bounds__(256, 4) k4c_scan(const float* __restrict__ A_log,
                                                   const float* __restrict__ conv_w,
                                                   const float* __restrict__ conv_b,
                                                   const float* __restrict__ dt_w,
                                                   const float* __restrict__ dt_b,
                                                   const float* __restrict__ D_skip)
{
    __shared__ ScanShared sh;
    int bi = blockIdx.x;
    int half = bi & 1, c = (bi >> 1) & 63, ib = bi >> 7;
    int i = ib >> 1, b = ib & 1;
    int tid = threadIdx.x;
    int d = half * 256 + tid;
    float4 wv = *(const float4*)&conv_w[((size_t)i * 512 + d) * 4];
    float cbv = conv_b[i * 512 + d];
    ull dtw2[8];
#pragma unroll
    for (int r = 0; r < 16; r += 4) {
        float4 v = *(const float4*)&dt_w[((size_t)i * 512 + d) * 16 + r];
        dtw2[r / 2]     = pack2(v.x, v.y);
        dtw2[r / 2 + 1] = pack2(v.z, v.w);
    }
    float dtb = dt_b[i * 512 + d];
    float Dsk = D_skip[i * 512 + d];
    bool fast = check_fast(A_log, i, d);
    float S;
    size_t base = (((size_t)ib * NCH + c) * 512 + d) * 16;
    if (fast) {
        ull h2[8];
        const ull* hb = (const ull*)&g_hin[base];
#pragma unroll
        for (int j = 0; j < 8; j++) h2[j] = hb[j];
        switch (i) {
        case 0: scan_fast<11, false, true>(&sh, ib, b, c, d, tid, wv, cbv, dtw2, dtb, Dsk, h2, &S); break;
        case 1: scan_fast<11, true,  true>(&sh, ib, b, c, d, tid, wv, cbv, dtw2, dtb, Dsk, h2, &S); break;
        case 2: scan_fast<6,  false, true>(&sh, ib, b, c, d, tid, wv, cbv, dtw2, dtb, Dsk, h2, &S); break;
        case 3: scan_fast<6,  true,  true>(&sh, ib, b, c, d, tid, wv, cbv, dtw2, dtb, Dsk, h2, &S); break;
        case 4: scan_fast<4,  false, true>(&sh, ib, b, c, d, tid, wv, cbv, dtw2, dtb, Dsk, h2, &S); break;
        default: scan_fast<4, true,  true>(&sh, ib, b, c, d, tid, wv, cbv, dtw2, dtb, Dsk, h2, &S); break;
        }
    } else {
        int sft = (i < 2) ? 11 : ((i < 4) ? 6 : 4);
        int rev = i & 1;
        int msk = (1 << sft) - 1;
        float h[16];
#pragma unroll
        for (int n = 0; n < 16; n++) h[n] = g_hin[base + n];
        scan_slow<true>(&sh, ib, b, c, d, tid, sft, rev, msk, wv, cbv, dtw2, dtb, A_log, Dsk, h, &S);
    }
}

// ---------------- K6: out[m][o] = sum_k total[m][k]*out_w[o][k] (M=4096,N=256,K=512) ----------------
__global__ void __launch_bounds__(256) k6_gemm_out(const float* __restrict__ out_w,
                                                   float* __restrict__ out)
{
    __shared__ __align__(16) float sa[16][132];
    __shared__ __align__(16) float sb[16][68];
    int m0 = blockIdx.x * 128, o0 = blockIdx.y * 64;
    int tid = threadIdx.x;
    int tx = tid & 15, ty = tid >> 4;
    ull acc[8][2];
#pragma unroll
    for (int ii = 0; ii < 8; ii++) { acc[ii][0] = 0ull; acc[ii][1] = 0ull; }
    int rowa = tid >> 1, kh = (tid & 1) * 8;
    int rowb = tid >> 2, kq = (tid & 3) * 4;
    for (int k0 = 0; k0 < 512; k0 += 16) {
#pragma unroll
        for (int q = 0; q < 2; q++) {
            float4 v = *(const float4*)&g_total[(size_t)(m0 + rowa) * 512 + k0 + kh + q * 4];
            sa[kh + q * 4 + 0][rowa] = v.x; sa[kh + q * 4 + 1][rowa] = v.y;
            sa[kh + q * 4 + 2][rowa] = v.z; sa[kh + q * 4 + 3][rowa] = v.w;
        }
        {
            float4 w = *(const float4*)&out_w[(size_t)(o0 + rowb) * 512 + k0 + kq];
            sb[kq + 0][rowb] = w.x; sb[kq + 1][rowb] = w.y;
            sb[kq + 2][rowb] = w.z; sb[kq + 3][rowb] = w.w;
        }
        __syncthreads();
#pragma unroll
        for (int kk = 0; kk < 16; kk++) {
            float4 a0 = *(float4*)&sa[kk][ty * 8];
            float4 a1 = *(float4*)&sa[kk][ty * 8 + 4];
            float4 bv = *(float4*)&sb[kk][tx * 4];
            ull bp[2] = {pack2(bv.x, bv.y), pack2(bv.z, bv.w)};
            float av[8] = {a0.x, a0.y, a0.z, a0.w, a1.x, a1.y, a1.z, a1.w};
#pragma unroll
            for (int ii = 0; ii < 8; ii++) {
                ull ap = pack2(av[ii], av[ii]);
                ffma2(acc[ii][0], ap, bp[0]);
                ffma2(acc[ii][1], ap, bp[1]);
            }
        }
        __syncthreads();
    }
#pragma unroll
    for (int ii = 0; ii < 8; ii++) {
        float2 c0 = unpack2(acc[ii][0]), c1 = unpack2(acc[ii][1]);
        float4 v = make_float4(c0.x, c0.y, c1.x, c1.y);
        *(float4*)&out[(size_t)(m0 + ty * 8 + ii) * 256 + o0 + tx * 4] = v;
    }
}

extern "C" void kernel_launch(void* const* d_in, const int* in_sizes, int n_in,
                              void* d_out, int out_size)
{
    const float* hs      = (const float*)d_in[0];
    const float* in_w    = (const float*)d_in[1];
    const float* out_w   = (const float*)d_in[2];
    const float* conv_w  = (const float*)d_in[3];
    const float* conv_b  = (const float*)d_in[4];
    const float* xproj_w = (const float*)d_in[5];
    const float* dt_w    = (const float*)d_in[6];
    const float* dt_b    = (const float*)d_in[7];
    const float* A_log   = (const float*)d_in[8];
    const float* D_skip  = (const float*)d_in[9];
    float* out = (float*)d_out;

    k0_zero<<<2048, 256>>>();
    k1_gemm_in<<<dim3(32, 8), 256>>>(hs, in_w);
    k3a_xproj<<<dim3(32, 12), 256>>>(xproj_w, conv_w, conv_b);
    k4a_chunk<<<1536, 256>>>(A_log, conv_w, conv_b, dt_w, dt_b);
    k4b_carry<<<384, 256>>>();
    k4c_scan<<<1536, 256>>>(A_log, conv_w, conv_b, dt_w, dt_b, D_skip);
    k6_gemm_out<<<dim3(32, 4), 256>>>(out_w, out);
}

// round 15
// speedup vs baseline: 1.0070x; 1.0070x over previous
#include <cuda_runtime.h>
#include <math.h>

// Mamba 6-branch fused pipeline: chunked parallel scan (fp32/f32x2) + 3xTF32 tensor-core GEMMs.
#define LSEQ 2048
#define DI   512
#define NIB  12
#define LC   32
#define NCH  64

typedef unsigned long long ull;

// -------- scratch (device globals) --------
__device__ float g_xz[2 * LSEQ * 1024];        // [b][l][e]
__device__ float g_dtlow[NIB * LSEQ * 16];     // [ib][t][r]
__device__ float g_bcs[NIB * LSEQ * 32];       // [ib][t][s] s<16:B, s>=16:C
__device__ float g_P[NIB * NCH * DI * 16];
__device__ float g_q[NIB * NCH * DI * 16];
__device__ float g_hin[NIB * NCH * DI * 16];
__device__ float g_total[2 * LSEQ * DI];       // [b][l][d]

__device__ __forceinline__ float silu_f(float v) {
    float e = __expf(-fabsf(v));
    return ((v >= 0.f) ? v : v * e) / (1.f + e);
}
__device__ __forceinline__ int perm_idx(int tau, int rev, int sft, int msk) {
    int base = rev ? (2047 - tau) : tau;
    return ((base & msk) << (11 - sft)) | (base >> sft);
}
__device__ __forceinline__ ull pack2(float lo, float hi) {
    ull r; asm("mov.b64 %0, {%1,%2};" : "=l"(r) : "f"(lo), "f"(hi)); return r;
}
__device__ __forceinline__ void ffma2(ull& d, ull a, ull b) {
    asm("fma.rn.f32x2 %0, %1, %2, %0;" : "+l"(d) : "l"(a), "l"(b));
}
__device__ __forceinline__ ull ffma2_3(ull a, ull b, ull c) {
    ull r; asm("fma.rn.f32x2 %0, %1, %2, %3;" : "=l"(r) : "l"(a), "l"(b), "l"(c)); return r;
}
__device__ __forceinline__ ull fmul2(ull a, ull b) {
    ull r; asm("mul.rn.f32x2 %0, %1, %2;" : "=l"(r) : "l"(a), "l"(b)); return r;
}
__device__ __forceinline__ float2 unpack2(ull v) {
    float2 f; asm("mov.b64 {%0,%1}, %2;" : "=f"(f.x), "=f"(f.y) : "l"(v)); return f;
}

// ---------------- K0: zero g_total ----------------
__global__ void __launch_bounds__(256) k0_zero()
{
    int gid = blockIdx.x * 256 + threadIdx.x;
    *(float4*)&g_total[(size_t)gid * 4] = make_float4(0.f, 0.f, 0.f, 0.f);
}

// ================= 3xTF32 tensor-core GEMM =================
// C[m][n] = sum_k A[m][k] * B[n][k];  A:[M][KTOT], B:[N][KTOT], C row stride LDC.
// Block tile: 128(m) x 2*NT*8(n). Warps: 4(m) x 2(n); warp tile 32(m) x NT*8(n).
__device__ __forceinline__ void cvt_hilo(float x, float* hi, float* lo) {
    unsigned h; asm("cvt.rna.tf32.f32 %0, %1;" : "=r"(h) : "f"(x));
    float hf = __uint_as_float(h);
    unsigned l; asm("cvt.rna.tf32.f32 %0, %1;" : "=r"(l) : "f"(x - hf));
    *hi = hf; *lo = __uint_as_float(l);
}
__device__ __forceinline__ void mma_tf32(float* d, const unsigned* a, unsigned b0, unsigned b1) {
    asm volatile("mma.sync.aligned.m16n8k8.row.col.f32.tf32.tf32.f32 "
                 "{%0,%1,%2,%3}, {%4,%5,%6,%7}, {%8,%9}, {%0,%1,%2,%3};"
                 : "+f"(d[0]), "+f"(d[1]), "+f"(d[2]), "+f"(d[3])
                 : "r"(a[0]), "r"(a[1]), "r"(a[2]), "r"(a[3]), "r"(b0), "r"(b1));
}

template<int KTOT, int NT, int LDC>
__global__ void __launch_bounds__(256) gemm3xtf32(const float* __restrict__ A,
                                                  const float* __restrict__ B,
                                                  float* __restrict__ C)
{
    constexpr int NTILE = 2 * NT * 8;
    __shared__ __align__(16) float sa_hi[128][20];
    __shared__ __align__(16) float sa_lo[128][20];
    __shared__ __align__(16) float sb_hi[NTILE][20];
    __shared__ __align__(16) float sb_lo[NTILE][20];
    int m0 = blockIdx.x * 128, n0 = blockIdx.y * NTILE;
    int tid = threadIdx.x;
    int lane = tid & 31, wid = tid >> 5;
    int wm = wid & 3, wn = wid >> 2;
    int g = lane >> 2, t4 = lane & 3;
    float d[2][NT][4];
#pragma unroll
    for (int mt = 0; mt < 2; mt++)
#pragma unroll
        for (int nt = 0; nt < NT; nt++)
#pragma unroll
            for (int r = 0; r < 4; r++) d[mt][nt][r] = 0.f;

    for (int kc = 0; kc < KTOT / 16; kc++) {
        {   // stage A: 128x16 (2 threads/row, 8 floats each)
            int row = tid >> 1, kq8 = (tid & 1) * 8;
            const float* src = A + (size_t)(m0 + row) * KTOT + kc * 16 + kq8;
            float4 v0 = *(const float4*)src;
            float4 v1 = *(const float4*)(src + 4);
            float* hd = &sa_hi[row][kq8];
            float* ld = &sa_lo[row][kq8];
            cvt_hilo(v0.x, hd + 0, ld + 0); cvt_hilo(v0.y, hd + 1, ld + 1);
            cvt_hilo(v0.z, hd + 2, ld + 2); cvt_hilo(v0.w, hd + 3, ld + 3);
            cvt_hilo(v1.x, hd + 4, ld + 4); cvt_hilo(v1.y, hd + 5, ld + 5);
            cvt_hilo(v1.z, hd + 6, ld + 6); cvt_hilo(v1.w, hd + 7, ld + 7);
        }
        // stage B: NTILE x 16
        for (int idx = tid * 8; idx < NTILE * 16; idx += 2048) {
            int row = idx >> 4, kq8 = idx & 15;
            const float* src = B + (size_t)(n0 + row) * KTOT + kc * 16 + kq8;
            float4 v0 = *(const float4*)src;
            float4 v1 = *(const float4*)(src + 4);
            float* hd = &sb_hi[row][kq8];
            float* ld = &sb_lo[row][kq8];
            cvt_hilo(v0.x, hd + 0, ld + 0); cvt_hilo(v0.y, hd + 1, ld + 1);
            cvt_hilo(v0.z, hd + 2, ld + 2); cvt_hilo(v0.w, hd + 3, ld + 3);
            cvt_hilo(v1.x, hd + 4, ld + 4); cvt_hilo(v1.y, hd + 5, ld + 5);
            cvt_hilo(v1.z, hd + 6, ld + 6); cvt_hilo(v1.w, hd + 7, ld + 7);
        }
        __syncthreads();
#pragma unroll
        for (int kq = 0; kq < 2; kq++) {
            int kb = kq * 8 + t4;
            unsigned ah[2][4], al[2][4];
#pragma unroll
            for (int mt = 0; mt < 2; mt++) {
                int mr = wm * 32 + mt * 16 + g;
                ah[mt][0] = __float_as_uint(sa_hi[mr][kb]);
                ah[mt][1] = __float_as_uint(sa_hi[mr + 8][kb]);
                ah[mt][2] = __float_as_uint(sa_hi[mr][kb + 4]);
                ah[mt][3] = __float_as_uint(sa_hi[mr + 8][kb + 4]);
                al[mt][0] = __float_as_uint(sa_lo[mr][kb]);
                al[mt][1] = __float_as_uint(sa_lo[mr + 8][kb]);
                al[mt][2] = __float_as_uint(sa_lo[mr][kb + 4]);
                al[mt][3] = __float_as_uint(sa_lo[mr + 8][kb + 4]);
            }
#pragma unroll
            for (int nt = 0; nt < NT; nt++) {
                int nc = wn * NT * 8 + nt * 8 + g;
                unsigned bh0 = __float_as_uint(sb_hi[nc][kb]);
                unsigned bh1 = __float_as_uint(sb_hi[nc][kb + 4]);
                unsigned bl0 = __float_as_uint(sb_lo[nc][kb]);
                unsigned bl1 = __float_as_uint(sb_lo[nc][kb + 4]);
#pragma unroll
                for (int mt = 0; mt < 2; mt++) {
                    mma_tf32(d[mt][nt], ah[mt], bl0, bl1);   // Ahi*Blo
                    mma_tf32(d[mt][nt], al[mt], bh0, bh1);   // Alo*Bhi
                    mma_tf32(d[mt][nt], ah[mt], bh0, bh1);   // Ahi*Bhi
                }
            }
        }
        __syncthreads();
    }
#pragma unroll
    for (int mt = 0; mt < 2; mt++) {
#pragma unroll
        for (int nt = 0; nt < NT; nt++) {
            int m = m0 + wm * 32 + mt * 16 + g;
            int n = n0 + wn * NT * 8 + nt * 8 + 2 * t4;
            *(float2*)&C[(size_t)m * LDC + n]       = make_float2(d[mt][nt][0], d[mt][nt][1]);
            *(float2*)&C[(size_t)(m + 8) * LDC + n] = make_float2(d[mt][nt][2], d[mt][nt][3]);
        }
    }
}

// ---------------- K3a: fused conv+silu u, x_dbl[ib][t][r] = sum_d u[t][d]*xproj_w[i][r][d] ----------------
__global__ void __launch_bounds__(256) k3a_xproj(const float* __restrict__ xproj_w,
                                                 const float* __restrict__ conv_w,
                                                 const float* __restrict__ conv_b)
{
    __shared__ float su[64][65];
    __shared__ float sw[48][65];
    int ib = blockIdx.y, i = ib >> 1, b = ib & 1;
    int t0 = blockIdx.x * 64;
    int tid = threadIdx.x;
    int tx = tid & 15, ty = tid >> 4;
    int sft = (i < 2) ? 11 : ((i < 4) ? 6 : 4);
    int rev = i & 1;
    int msk = (1 << sft) - 1;
    const float* xb = g_xz + (size_t)b * LSEQ * 1024;
    ull acc2[2][3];
#pragma unroll
    for (int ii = 0; ii < 2; ii++)
#pragma unroll
        for (int j = 0; j < 3; j++) acc2[ii][j] = 0ull;

    for (int dk = 0; dk < 512; dk += 64) {
#pragma unroll
        for (int p = 0; p < 4; p++) {
            int lin = tid + p * 256;
            int tt = lin >> 4, dq = (lin & 15) * 4;
            int dcol = dk + dq;
            float4 wv0 = *(const float4*)&conv_w[((size_t)i * 512 + dcol + 0) * 4];
            float4 wv1 = *(const float4*)&conv_w[((size_t)i * 512 + dcol + 1) * 4];
            float4 wv2 = *(const float4*)&conv_w[((size_t)i * 512 + dcol + 2) * 4];
            float4 wv3 = *(const float4*)&conv_w[((size_t)i * 512 + dcol + 3) * 4];
            float4 a = *(const float4*)&conv_b[i * 512 + dcol];
#pragma unroll
            for (int k = 0; k < 4; k++) {
                int tau = t0 + tt - 3 + k;
                if (tau >= 0) {
                    int l = perm_idx(tau, rev, sft, msk);
                    float4 xv = *(const float4*)&xb[(size_t)l * 1024 + dcol];
                    float w0 = (k == 0) ? wv0.x : (k == 1) ? wv0.y : (k == 2) ? wv0.z : wv0.w;
                    float w1 = (k == 0) ? wv1.x : (k == 1) ? wv1.y : (k == 2) ? wv1.z : wv1.w;
                    float w2 = (k == 0) ? wv2.x : (k == 1) ? wv2.y : (k == 2) ? wv2.z : wv2.w;
                    float w3 = (k == 0) ? wv3.x : (k == 1) ? wv3.y : (k == 2) ? wv3.z : wv3.w;
                    a.x = fmaf(w0, xv.x, a.x);
                    a.y = fmaf(w1, xv.y, a.y);
                    a.z = fmaf(w2, xv.z, a.z);
                    a.w = fmaf(w3, xv.w, a.w);
                }
            }
            su[tt][dq + 0] = silu_f(a.x);
            su[tt][dq + 1] = silu_f(a.y);
            su[tt][dq + 2] = silu_f(a.z);
            su[tt][dq + 3] = silu_f(a.w);
        }
#pragma unroll
        for (int p = 0; p < 3; p++) {
            int lin = tid + p * 256;
            int r = lin >> 4, dq = lin & 15;
            float4 v = *(const float4*)&xproj_w[((size_t)i * 48 + r) * 512 + dk + dq * 4];
            sw[r][dq * 4 + 0] = v.x; sw[r][dq * 4 + 1] = v.y;
            sw[r][dq * 4 + 2] = v.z; sw[r][dq * 4 + 3] = v.w;
        }
        __syncthreads();
#pragma unroll 8
        for (int dd = 0; dd < 64; dd++) {
            ull up0 = pack2(su[tx * 4 + 0][dd], su[tx * 4 + 1][dd]);
            ull up1 = pack2(su[tx * 4 + 2][dd], su[tx * 4 + 3][dd]);
#pragma unroll
            for (int j = 0; j < 3; j++) {
                float wvv = sw[ty * 3 + j][dd];
                ull wvp = pack2(wvv, wvv);
                ffma2(acc2[0][j], up0, wvp);
                ffma2(acc2[1][j], up1, wvp);
            }
        }
        __syncthreads();
    }
#pragma unroll
    for (int j = 0; j < 3; j++) {
        float2 lo = unpack2(acc2[0][j]);
        float2 hi = unpack2(acc2[1][j]);
        float vals[4] = {lo.x, lo.y, hi.x, hi.y};
        int r = ty * 3 + j;
#pragma unroll
        for (int ii = 0; ii < 4; ii++) {
            int t = t0 + tx * 4 + ii;
            float v = vals[ii];
            if (r < 16) g_dtlow[((size_t)ib * LSEQ + t) * 16 + r] = v;
            else        g_bcs[((size_t)ib * LSEQ + t) * 32 + (r - 16)] = v;
        }
    }
}

// ---------------- scan shared staging ----------------
struct __align__(16) ScanShared {
    float sdt[32][20];
    float sbc[32][36];
};

__device__ __forceinline__ void stage_tile(ScanShared* sh, int ib, int tb, int tid, bool passc)
{
    __syncthreads();
    if (tid < 128) {
        int tt = tid >> 2, r4 = (tid & 3) * 4;
        *(float4*)&sh->sdt[tt][r4] =
            *(const float4*)&g_dtlow[((size_t)ib * LSEQ + tb + tt) * 16 + r4];
    }
    if (passc) {
        int tt = tid >> 3, s4 = (tid & 7) * 4;
        *(float4*)&sh->sbc[tt][s4] =
            *(const float4*)&g_bcs[((size_t)ib * LSEQ + tb + tt) * 32 + s4];
    } else if (tid >= 128) {
        int q = tid - 128;
        int tt = q >> 2, r4 = (q & 3) * 4;
        *(float4*)&sh->sbc[tt][r4] =
            *(const float4*)&g_bcs[((size_t)ib * LSEQ + tb + tt) * 32 + r4];
    }
    __syncthreads();
}

// ---------------- fast (A[n]=-(n+1)) scan body; SFT/REV compile-time specialized ----------------
template<int SFT, bool REV, bool PASSC>
__device__ __forceinline__ void scan_fast(
    ScanShared* sh, int ib, int b, int c, int d, int tid,
    float4 wv, float cbv, const ull* dtw2, float dtb,
    float Dsk, ull* h2, float* Sout)
{
    constexpr int MSK = (1 << SFT) - 1;
    constexpr int LSTRIDE = (REV ? -1 : 1) * (1 << (11 - SFT));
    constexpr int RMASK = (SFT == 6) ? 31 : 15;
    const float* xb = g_xz + (size_t)b * LSEQ * 1024 + d;
    const float* zb = xb + 512;
    float x3 = 0.f, x2 = 0.f, x1 = 0.f;
    int t0c = c * LC;
    if (t0c >= 3) {
        x3 = xb[(size_t)perm_idx(t0c - 3, REV, SFT, MSK) * 1024];
        x2 = xb[(size_t)perm_idx(t0c - 2, REV, SFT, MSK) * 1024];
        x1 = xb[(size_t)perm_idx(t0c - 1, REV, SFT, MSK) * 1024];
    }
    int l = perm_idx(t0c, REV, SFT, MSK);
    float xcur = xb[(size_t)l * 1024];
    float S = 0.f;
    float* totb = g_total + (size_t)b * LSEQ * 512 + d;
    for (int sub = 0; sub < LC / 32; sub++) {
        int tb = t0c + sub * 32;
        stage_tile(sh, ib, tb, tid, PASSC);
#pragma unroll 2
        for (int tt = 0; tt < 32; tt++) {
            int t = tb + tt;
            int tn = t + 1;
            int lnext;
            if (SFT == 11) lnext = l + LSTRIDE;
            else lnext = ((tn & RMASK) == 0) ? perm_idx(tn, REV, SFT, MSK) : (l + LSTRIDE);
            float xnext = (tn < 2048) ? xb[(size_t)lnext * 1024] : 0.f;
            float ua = fmaf(wv.x, x3, fmaf(wv.y, x2, fmaf(wv.z, x1, fmaf(wv.w, xcur, cbv))));
            x3 = x2; x2 = x1; x1 = xcur;
            float u = silu_f(ua);
            const ull* qd = (const ull*)&sh->sdt[tt][0];
            ull a2 = 0ull;
#pragma unroll
            for (int j = 0; j < 8; j++) ffma2(a2, dtw2[j], qd[j]);
            float2 as_ = unpack2(a2);
            float a = dtb + as_.x + as_.y;
            float delta = fmaxf(a, 0.f) + __logf(1.f + __expf(-fabsf(a)));
            S += delta;
            float E = __expf(-delta);
            float E2 = E * E;
            ull e2p = pack2(E2, E2);
            ull dA = pack2(E, E2);
            float dub = delta * u;
            ull dubp = pack2(dub, dub);
            const ull* bp = (const ull*)&sh->sbc[tt][0];
            const ull* cp = (const ull*)&sh->sbc[tt][16];
            ull y2 = 0ull;
#pragma unroll
            for (int j = 0; j < 8; j++) {
                h2[j] = ffma2_3(dA, h2[j], fmul2(dubp, bp[j]));
                if (PASSC) ffma2(y2, h2[j], cp[j]);
                if (j < 7) dA = fmul2(dA, e2p);
            }
            if (PASSC) {
                float2 yy = unpack2(y2);
                float y = yy.x + yy.y;
                float z = zb[(size_t)l * 1024];
                float outv = (y + u * Dsk) * silu_f(z);
                int lout;
                if (SFT == 11 && !REV)      lout = t;
                else if (SFT == 11)         lout = 2047 - t;
                else if (SFT == 6)          lout = ((t & 63) << 5) | (t >> 6);
                else                        lout = ((t & 15) << 7) | (t >> 4);
                atomicAdd(&totb[(size_t)lout * 512], outv);
            }
            l = lnext; xcur = xnext;
        }
    }
    *Sout = S;
}

// ---------------- slow fallback (general A), scalar ----------------
template<bool PASSC>
__device__ __noinline__ void scan_slow(
    ScanShared* sh, int ib, int b, int c, int d, int tid,
    int sft, int rev, int msk,
    float4 wv, float cbv, const ull* dtw2, float dtb,
    const float* A_log, float Dsk, float* h, float* Sout)
{
    int i = ib >> 1;
    float Av[16];
#pragma unroll
    for (int n = 0; n < 16; n++) Av[n] = -__expf(A_log[((size_t)i * 512 + d) * 16 + n]);
    const float* xb = g_xz + (size_t)b * LSEQ * 1024 + d;
    const float* zb = xb + 512;
    float x3 = 0.f, x2 = 0.f, x1 = 0.f;
    int t0c = c * LC;
    if (t0c >= 3) {
        x3 = xb[(size_t)perm_idx(t0c - 3, rev, sft, msk) * 1024];
        x2 = xb[(size_t)perm_idx(t0c - 2, rev, sft, msk) * 1024];
        x1 = xb[(size_t)perm_idx(t0c - 1, rev, sft, msk) * 1024];
    }
    float S = 0.f;
    float* totb = g_total + (size_t)b * LSEQ * 512 + d;
    for (int sub = 0; sub < LC / 32; sub++) {
        int tb = t0c + sub * 32;
        stage_tile(sh, ib, tb, tid, PASSC);
        for (int tt = 0; tt < 32; tt++) {
            int t = tb + tt;
            int l = perm_idx(t, rev, sft, msk);
            float xv = xb[(size_t)l * 1024];
            float ua = fmaf(wv.x, x3, fmaf(wv.y, x2, fmaf(wv.z, x1, fmaf(wv.w, xv, cbv))));
            x3 = x2; x2 = x1; x1 = xv;
            float u = silu_f(ua);
            const ull* qd = (const ull*)&sh->sdt[tt][0];
            ull a2 = 0ull;
#pragma unroll
            for (int j = 0; j < 8; j++) ffma2(a2, dtw2[j], qd[j]);
            float2 as_ = unpack2(a2);
            float a = dtb + as_.x + as_.y;
            float delta = fmaxf(a, 0.f) + __logf(1.f + __expf(-fabsf(a)));
            S += delta;
            float dub = delta * u;
            float y = 0.f;
#pragma unroll
            for (int n = 0; n < 16; n++) {
                float bn = sh->sbc[tt][n];
                h[n] = fmaf(__expf(delta * Av[n]), h[n], dub * bn);
                if (PASSC) y = fmaf(h[n], sh->sbc[tt][16 + n], y);
            }
            if (PASSC) {
                float z = zb[(size_t)l * 1024];
                float outv = (y + u * Dsk) * silu_f(z);
                int i2 = ib >> 1;
                int lout;
                if (i2 == 0)      lout = t;
                else if (i2 == 1) lout = 2047 - t;
                else if (i2 < 4)  lout = ((t & 63) << 5) | (t >> 6);
                else              lout = ((t & 15) << 7) | (t >> 4);
                atomicAdd(&totb[(size_t)lout * 512], outv);
            }
        }
    }
    *Sout = S;
}

__device__ __forceinline__ bool check_fast(const float* A_log, int i, int d) {
    bool fast = true;
#pragma unroll
    for (int n = 0; n < 16; n++) {
        float Av = __expf(A_log[((size_t)i * 512 + d) * 16 + n]);
        fast = fast && (fabsf(Av - (float)(n + 1)) < 1e-4f * (float)(n + 1));
    }
    return fast;
}

__global__ void __launch_bounds__(256, 4) k4a_chunk(const float* __restrict__ A_log,
                                                    const float* __restrict__ conv_w,
                                                    const float* __restrict__ conv_b,
                                                    const float* __restrict__ dt_w,
                                                    const float* __restrict__ dt_b)
{
    __shared__ ScanShared sh;
    int bi = blockIdx.x;                  // 1536 = 12 ib * 64 c * 2 half
    int half = bi & 1, c = (bi >> 1) & 63, ib = bi >> 7;
    int i = ib >> 1, b = ib & 1;
    int tid = threadIdx.x;
    int d = half * 256 + tid;
    float4 wv = *(const float4*)&conv_w[((size_t)i * 512 + d) * 4];
    float cbv = conv_b[i * 512 + d];
    ull dtw2[8];
#pragma unroll
    for (int r = 0; r < 16; r += 4) {
        float4 v = *(const float4*)&dt_w[((size_t)i * 512 + d) * 16 + r];
        dtw2[r / 2]     = pack2(v.x, v.y);
        dtw2[r / 2 + 1] = pack2(v.z, v.w);
    }
    float dtb = dt_b[i * 512 + d];
    bool fast = check_fast(A_log, i, d);
    float S = 0.f;
    size_t base = (((size_t)ib * NCH + c) * 512 + d) * 16;
    if (fast) {
        ull h2[8];
#pragma unroll
        for (int j = 0; j < 8; j++) h2[j] = 0ull;
        switch (i) {
        case 0: scan_fast<11, false, false>(&sh, ib, b, c, d, tid, wv, cbv, dtw2, dtb, 0.f, h2, &S); break;
        case 1: scan_fast<11, true,  false>(&sh, ib, b, c, d, tid, wv, cbv, dtw2, dtb, 0.f, h2, &S); break;
        case 2: scan_fast<6,  false, false>(&sh, ib, b, c, d, tid, wv, cbv, dtw2, dtb, 0.f, h2, &S); break;
        case 3: scan_fast<6,  true,  false>(&sh, ib, b, c, d, tid, wv, cbv, dtw2, dtb, 0.f, h2, &S); break;
        case 4: scan_fast<4,  false, false>(&sh, ib, b, c, d, tid, wv, cbv, dtw2, dtb, 0.f, h2, &S); break;
        default: scan_fast<4, true,  false>(&sh, ib, b, c, d, tid, wv, cbv, dtw2, dtb, 0.f, h2, &S); break;
        }
        ull* qb = (ull*)&g_q[base];
#pragma unroll
        for (int j = 0; j < 8; j++) qb[j] = h2[j];
        float F = __expf(-S);
        float F2 = F * F;
        ull f2p = pack2(F2, F2);
        ull P = pack2(F, F2);
        ull* pb = (ull*)&g_P[base];
#pragma unroll
        for (int j = 0; j < 8; j++) {
            pb[j] = P;
            if (j < 7) P = fmul2(P, f2p);
        }
    } else {
        int sft = (i < 2) ? 11 : ((i < 4) ? 6 : 4);
        int rev = i & 1;
        int msk = (1 << sft) - 1;
        float h[16];
#pragma unroll
        for (int n = 0; n < 16; n++) h[n] = 0.f;
        scan_slow<false>(&sh, ib, b, c, d, tid, sft, rev, msk, wv, cbv, dtw2, dtb, A_log, 0.f, h, &S);
#pragma unroll
        for (int n = 0; n < 16; n++) {
            float Av = -__expf(A_log[((size_t)i * 512 + d) * 16 + n]);
            g_P[base + n] = __expf(Av * S);
            g_q[base + n] = h[n];
        }
    }
}

// ---------------- K4b: inter-chunk scan (64 steps, prefetched batches of 16) ----------------
__global__ void __launch_bounds__(256) k4b_carry()
{
    int gid = blockIdx.x * 256 + threadIdx.x;   // 98304 = 12*512*16
    size_t base0 = (size_t)gid % (512 * 16);
    int ib = gid / (512 * 16);
    size_t stride = (size_t)512 * 16;
    size_t b0 = (size_t)ib * NCH * stride + base0;
    float h = 0.f;
#pragma unroll
    for (int batch = 0; batch < NCH / 16; batch++) {
        float P[16], q[16];
#pragma unroll
        for (int j = 0; j < 16; j++) {
            size_t idx = b0 + (size_t)(batch * 16 + j) * stride;
            P[j] = g_P[idx];
            q[j] = g_q[idx];
        }
#pragma unroll
        for (int j = 0; j < 16; j++) {
            size_t idx = b0 + (size_t)(batch * 16 + j) * stride;
            g_hin[idx] = h;
            h = fmaf(P[j], h, q[j]);
        }
    }
}

__global__ void __launch_bounds__(256, 4) k4c_scan(const float* __restrict__ A_log,
                                                   const float* __restrict__ conv_w,
                                                   const float* __restrict__ conv_b,
                                                   const float* __restrict__ dt_w,
                                                   const float* __restrict__ dt_b,
                                                   const float* __restrict__ D_skip)
{
    __shared__ ScanShared sh;
    int bi = blockIdx.x;
    int half = bi & 1, c = (bi >> 1) & 63, ib = bi >> 7;
    int i = ib >> 1, b = ib & 1;
    int tid = threadIdx.x;
    int d = half * 256 + tid;
    float4 wv = *(const float4*)&conv_w[((size_t)i * 512 + d) * 4];
    float cbv = conv_b[i * 512 + d];
    ull dtw2[8];
#pragma unroll
    for (int r = 0; r < 16; r += 4) {
        float4 v = *(const float4*)&dt_w[((size_t)i * 512 + d) * 16 + r];
        dtw2[r / 2]     = pack2(v.x, v.y);
        dtw2[r / 2 + 1] = pack2(v.z, v.w);
    }
    float dtb = dt_b[i * 512 + d];
    float Dsk = D_skip[i * 512 + d];
    bool fast = check_fast(A_log, i, d);
    float S;
    size_t base = (((size_t)ib * NCH + c) * 512 + d) * 16;
    if (fast) {
        ull h2[8];
        const ull* hb = (const ull*)&g_hin[base];
#pragma unroll
        for (int j = 0; j < 8; j++) h2[j] = hb[j];
        switch (i) {
        case 0: scan_fast<11, false, true>(&sh, ib, b, c, d, tid, wv, cbv, dtw2, dtb, Dsk, h2, &S); break;
        case 1: scan_fast<11, true,  true>(&sh, ib, b, c, d, tid, wv, cbv, dtw2, dtb, Dsk, h2, &S); break;
        case 2: scan_fast<6,  false, true>(&sh, ib, b, c, d, tid, wv, cbv, dtw2, dtb, Dsk, h2, &S); break;
        case 3: scan_fast<6,  true,  true>(&sh, ib, b, c, d, tid, wv, cbv, dtw2, dtb, Dsk, h2, &S); break;
        case 4: scan_fast<4,  false, true>(&sh, ib, b, c, d, tid, wv, cbv, dtw2, dtb, Dsk, h2, &S); break;
        default: scan_fast<4, true,  true>(&sh, ib, b, c, d, tid, wv, cbv, dtw2, dtb, Dsk, h2, &S); break;
        }
    } else {
        int sft = (i < 2) ? 11 : ((i < 4) ? 6 : 4);
        int rev = i & 1;
        int msk = (1 << sft) - 1;
        float h[16];
#pragma unroll
        for (int n = 0; n < 16; n++) h[n] = g_hin[base + n];
        scan_slow<true>(&sh, ib, b, c, d, tid, sft, rev, msk, wv, cbv, dtw2, dtb, A_log, Dsk, h, &S);
    }
}

extern "C" void kernel_launch(void* const* d_in, const int* in_sizes, int n_in,
                              void* d_out, int out_size)
{
    const float* hs      = (const float*)d_in[0];
    const float* in_w    = (const float*)d_in[1];
    const float* out_w   = (const float*)d_in[2];
    const float* conv_w  = (const float*)d_in[3];
    const float* conv_b  = (const float*)d_in[4];
    const float* xproj_w = (const float*)d_in[5];
    const float* dt_w    = (const float*)d_in[6];
    const float* dt_b    = (const float*)d_in[7];
    const float* A_log   = (const float*)d_in[8];
    const float* D_skip  = (const float*)d_in[9];
    float* out = (float*)d_out;

    // device-symbol addresses (host-side queries; graph-capture safe)
    float *g_xz_ptr, *g_total_ptr;
    cudaGetSymbolAddress((void**)&g_xz_ptr, g_xz);
    cudaGetSymbolAddress((void**)&g_total_ptr, g_total);

    k0_zero<<<2048, 256>>>();
    // K1: xz = hs @ in_w^T  (M=4096, N=1024, K=256), C row stride 1024
    gemm3xtf32<256, 8, 1024><<<dim3(32, 8), 256>>>(hs, in_w, g_xz_ptr);
    k3a_xproj<<<dim3(32, 12), 256>>>(xproj_w, conv_w, conv_b);
    k4a_chunk<<<1536, 256>>>(A_log, conv_w, conv_b, dt_w, dt_b);
    k4b_carry<<<384, 256>>>();
    k4c_scan<<<1536, 256>>>(A_log, conv_w, conv_b, dt_w, dt_b, D_skip);
    // K6: out = total @ out_w^T  (M=4096, N=256, K=512), C row stride 256
    gemm3xtf32<512, 4, 256><<<dim3(32, 4), 256>>>(g_total_ptr, out_w, out);
}